// round 1
// baseline (speedup 1.0000x reference)
#include <cuda_runtime.h>
#include <cuda_bf16.h>

// Problem constants
#define Bv  2
#define Hv  16
#define Sv  2048
#define DKv 64

// Tiling
#define BM 64          // queries per block
#define BN 64          // keys per tile
#define LD 68          // padded smem row stride (floats), 272B: 16B-aligned, conflict-breaking
#define NTHREADS 256

#define SMEM_FLOATS (4 * BM * LD)          // sQ, sKt, sV, sP
#define SMEM_BYTES  (SMEM_FLOATS * 4)      // 69632 bytes

// Fast exp on the FMA pipe (avoids MUFU throughput wall).
// Valid for x <= 0 (softmax args). Clamps to 2^-126 for very negative x.
__device__ __forceinline__ float fexp(float x) {
    float y = x * 1.4426950408889634f;          // log2(e)
    y = fmaxf(y, -126.0f);
    const float magic = 12582912.0f;            // 1.5 * 2^23
    float t = y + magic;                        // round-to-nearest in low bits
    int   n = __float_as_int(t) - 0x4B400000;   // integer part
    float f = y - (t - magic);                  // frac in [-0.5, 0.5]
    // 2^f via Taylor in f*ln2, |err| < 3e-6
    float p = 1.33336498e-3f;
    p = fmaf(p, f, 9.61011695e-3f);
    p = fmaf(p, f, 5.55036483e-2f);
    p = fmaf(p, f, 2.40226507e-1f);
    p = fmaf(p, f, 6.93147182e-1f);
    p = fmaf(p, f, 1.0f);
    return p * __int_as_float((n + 127) << 23);
}

__global__ __launch_bounds__(NTHREADS, 2)
void sdp_flash_kernel(const float* __restrict__ Q,
                      const float* __restrict__ K,
                      const float* __restrict__ V,
                      const float* __restrict__ Mask,
                      float* __restrict__ Out) {
    extern __shared__ float sm[];
    float* sQ  = sm;                 // [BM][LD]  row = query, col = dk
    float* sKt = sQ  + BM * LD;      // [DK][LD]  row = dk,    col = key   (transposed!)
    float* sV  = sKt + DKv * LD;     // [BN][LD]  row = key,   col = dk
    float* sP  = sV  + BN * LD;      // [BM][LD]  row = query, col = key

    const int tid = threadIdx.x;
    const int tx  = tid & 15;        // 0..15 -> 4 cols each
    const int ty  = tid >> 4;        // 0..15 -> 4 rows each
    const int tx4 = tx * 4;
    const int ty4 = ty * 4;

    const int h  = blockIdx.y;
    const int b  = blockIdx.z;
    const int q0 = blockIdx.x * BM;

    const size_t bh = (size_t)(b * Hv + h);
    const float* Qg  = Q + (bh * Sv + q0) * DKv;
    const float* Kg0 = K + bh * Sv * DKv;
    const float* Vg0 = V + bh * Sv * DKv;
    const float* Mg  = Mask + ((size_t)b * Sv + q0) * Sv;   // mask[b,0,q,:]

    // ---- Load Q tile once: [64 rows][64 dk], natural layout ----
    {
        const int r0 = tid >> 4;          // 0..15
        const int d4 = (tid & 15) * 4;    // 0..60
        #pragma unroll
        for (int r = 0; r < 4; r++) {
            const int row = r0 + r * 16;
            float4 v = *(const float4*)(Qg + row * DKv + d4);
            *(float4*)(sQ + row * LD + d4) = v;
        }
    }

    // Per-thread state: 4 query rows x 4 dk cols of O, plus row stats
    float o[4][4];
    float mrow[4], lrow[4];
    #pragma unroll
    for (int i = 0; i < 4; i++) {
        mrow[i] = -1e30f;
        lrow[i] = 0.0f;
        #pragma unroll
        for (int j = 0; j < 4; j++) o[i][j] = 0.0f;
    }

    const float scale = 0.125f;   // 1/sqrt(64)

    for (int kt = 0; kt < Sv / BN; kt++) {
        const float* Kg = Kg0 + (size_t)kt * BN * DKv;
        const float* Vg = Vg0 + (size_t)kt * BN * DKv;

        __syncthreads();   // previous iteration's PV GEMM done before overwriting sKt/sV

        // ---- Load K (transposed into sKt) and V (natural) ----
        {
            const int r0 = tid >> 4;
            const int d4 = (tid & 15) * 4;
            #pragma unroll
            for (int r = 0; r < 4; r++) {
                const int key = r0 + r * 16;
                float4 kv = *(const float4*)(Kg + key * DKv + d4);
                sKt[(d4 + 0) * LD + key] = kv.x;
                sKt[(d4 + 1) * LD + key] = kv.y;
                sKt[(d4 + 2) * LD + key] = kv.z;
                sKt[(d4 + 3) * LD + key] = kv.w;
                float4 vv = *(const float4*)(Vg + key * DKv + d4);
                *(float4*)(sV + key * LD + d4) = vv;
            }
        }

        // ---- Mask tile straight to registers (L2-resident across the 16 heads) ----
        float mk[4][4];
        #pragma unroll
        for (int i = 0; i < 4; i++) {
            float4 mv = *(const float4*)(Mg + (size_t)(ty4 + i) * Sv + kt * BN + tx4);
            mk[i][0] = mv.x; mk[i][1] = mv.y; mk[i][2] = mv.z; mk[i][3] = mv.w;
        }

        __syncthreads();   // K/V tiles visible

        // ---- S = Q @ K^T  (4x4 register tile) ----
        float acc[4][4];
        #pragma unroll
        for (int i = 0; i < 4; i++)
            #pragma unroll
            for (int j = 0; j < 4; j++) acc[i][j] = 0.0f;

        #pragma unroll
        for (int k4 = 0; k4 < DKv; k4 += 4) {
            float qr[4][4];
            #pragma unroll
            for (int i = 0; i < 4; i++) {
                float4 qv = *(const float4*)(sQ + (ty4 + i) * LD + k4);
                qr[i][0] = qv.x; qr[i][1] = qv.y; qr[i][2] = qv.z; qr[i][3] = qv.w;
            }
            #pragma unroll
            for (int u = 0; u < 4; u++) {
                float4 kv = *(const float4*)(sKt + (k4 + u) * LD + tx4);
                #pragma unroll
                for (int i = 0; i < 4; i++) {
                    acc[i][0] = fmaf(qr[i][u], kv.x, acc[i][0]);
                    acc[i][1] = fmaf(qr[i][u], kv.y, acc[i][1]);
                    acc[i][2] = fmaf(qr[i][u], kv.z, acc[i][2]);
                    acc[i][3] = fmaf(qr[i][u], kv.w, acc[i][3]);
                }
            }
        }

        // ---- Non-standard masking + streaming softmax update ----
        #pragma unroll
        for (int i = 0; i < 4; i++) {
            // apply scale * mask, then keep only strictly positive
            float s0 = acc[i][0] * scale * mk[i][0];
            float s1 = acc[i][1] * scale * mk[i][1];
            float s2 = acc[i][2] * scale * mk[i][2];
            float s3 = acc[i][3] * scale * mk[i][3];
            s0 = (s0 > 0.0f) ? s0 : -10000.0f;
            s1 = (s1 > 0.0f) ? s1 : -10000.0f;
            s2 = (s2 > 0.0f) ? s2 : -10000.0f;
            s3 = (s3 > 0.0f) ? s3 : -10000.0f;

            // row max across this thread's 4 cols, then across the 16 tx lanes
            float tmax = fmaxf(fmaxf(s0, s1), fmaxf(s2, s3));
            #pragma unroll
            for (int off = 1; off < 16; off <<= 1)
                tmax = fmaxf(tmax, __shfl_xor_sync(0xffffffffu, tmax, off));

            const float m_new = fmaxf(mrow[i], tmax);
            const float alpha = fexp(mrow[i] - m_new);

            float p0 = fexp(s0 - m_new);
            float p1 = fexp(s1 - m_new);
            float p2 = fexp(s2 - m_new);
            float p3 = fexp(s3 - m_new);

            float tsum = (p0 + p1) + (p2 + p3);
            #pragma unroll
            for (int off = 1; off < 16; off <<= 1)
                tsum += __shfl_xor_sync(0xffffffffu, tsum, off);

            lrow[i] = lrow[i] * alpha + tsum;
            mrow[i] = m_new;

            o[i][0] *= alpha; o[i][1] *= alpha; o[i][2] *= alpha; o[i][3] *= alpha;

            float4 pv = make_float4(p0, p1, p2, p3);
            *(float4*)(sP + (ty4 + i) * LD + tx4) = pv;
        }

        __syncthreads();   // P tile visible

        // ---- O += P @ V ----
        #pragma unroll
        for (int k4 = 0; k4 < BN; k4 += 4) {
            float pr[4][4];
            #pragma unroll
            for (int i = 0; i < 4; i++) {
                float4 pv = *(const float4*)(sP + (ty4 + i) * LD + k4);
                pr[i][0] = pv.x; pr[i][1] = pv.y; pr[i][2] = pv.z; pr[i][3] = pv.w;
            }
            #pragma unroll
            for (int u = 0; u < 4; u++) {
                float4 vv = *(const float4*)(sV + (k4 + u) * LD + tx4);
                #pragma unroll
                for (int i = 0; i < 4; i++) {
                    o[i][0] = fmaf(pr[i][u], vv.x, o[i][0]);
                    o[i][1] = fmaf(pr[i][u], vv.y, o[i][1]);
                    o[i][2] = fmaf(pr[i][u], vv.z, o[i][2]);
                    o[i][3] = fmaf(pr[i][u], vv.w, o[i][3]);
                }
            }
        }
    }

    // ---- Epilogue: normalize and store ----
    float* Og = Out + (bh * Sv + q0) * DKv;
    #pragma unroll
    for (int i = 0; i < 4; i++) {
        const float inv = 1.0f / lrow[i];
        float4 r = make_float4(o[i][0] * inv, o[i][1] * inv, o[i][2] * inv, o[i][3] * inv);
        *(float4*)(Og + (ty4 + i) * DKv + tx4) = r;
    }
}

extern "C" void kernel_launch(void* const* d_in, const int* in_sizes, int n_in,
                              void* d_out, int out_size) {
    const float* Q = (const float*)d_in[0];
    const float* K = (const float*)d_in[1];
    const float* V = (const float*)d_in[2];
    const float* M = (const float*)d_in[3];
    float* Out = (float*)d_out;

    cudaFuncSetAttribute(sdp_flash_kernel,
                         cudaFuncAttributeMaxDynamicSharedMemorySize, SMEM_BYTES);

    dim3 grid(Sv / BM, Hv, Bv);   // 32 x 16 x 2 = 1024 CTAs
    sdp_flash_kernel<<<grid, NTHREADS, SMEM_BYTES>>>(Q, K, V, M, Out);
}